// round 15
// baseline (speedup 1.0000x reference)
#include <cuda_runtime.h>
#include <math.h>

typedef unsigned long long u64;
typedef unsigned int u32;

// Scratch: N=20000
__device__ __align__(16) u32 g1_buf[81920000];    // g1 (N,64,128) bf16
__device__ __align__(16) u32 g2_buf[81920000];    // g2 (N,64,128) bf16
__device__ float gat_buf[1280000];                // gating (N,64)
__device__ __align__(16) float fw_buf[40960];     // l1w[l] @ W1  (5,64,128)
__device__ float b1w_buf[128];                    // l1b @ W1

__device__ __constant__ int c_deg[25] = {
    0, 1,1,1, 2,2,2,2,2, 3,3,3,3,3,3,3, 4,4,4,4,4,4,4,4,4
};
__device__ __constant__ float c_bw[25] = {
    0.f,
    1.f/12.f, 1.f/12.f, 1.f/12.f,
    1.f/20.f, 1.f/20.f, 1.f/20.f, 1.f/20.f, 1.f/20.f,
    1.f/28.f, 1.f/28.f, 1.f/28.f, 1.f/28.f, 1.f/28.f, 1.f/28.f, 1.f/28.f,
    1.f/36.f, 1.f/36.f, 1.f/36.f, 1.f/36.f, 1.f/36.f, 1.f/36.f, 1.f/36.f, 1.f/36.f, 1.f/36.f
};

__device__ __forceinline__ u64 ffma2(u64 a, u64 b, u64 c) {
    u64 d;
    asm("fma.rn.f32x2 %0, %1, %2, %3;" : "=l"(d) : "l"(a), "l"(b), "l"(c));
    return d;
}
__device__ __forceinline__ u64 dup2(float x) {
    u64 r; asm("mov.b64 %0, {%1, %1};" : "=l"(r) : "f"(x)); return r;
}
__device__ __forceinline__ float2 unpk(u64 v) {
    float2 f; asm("mov.b64 {%0, %1}, %2;" : "=f"(f.x), "=f"(f.y) : "l"(v)); return f;
}
__device__ __forceinline__ float silu_f(float v) {
    return v * (1.f / (1.f + __expf(-v)));
}
__device__ __forceinline__ u32 bpack(float lo, float hi) {
    u32 d; asm("cvt.rn.bf16x2.f32 %0, %1, %2;" : "=r"(d) : "f"(hi), "f"(lo)); return d;
}
__device__ __forceinline__ float blo(u32 p) { return __uint_as_float(p << 16); }
__device__ __forceinline__ float bhi(u32 p) { return __uint_as_float(p & 0xFFFF0000u); }

#define LDA  68
#define LDA2 36

template<int NQ, int KC, int LDAX>
__device__ __forceinline__ void gemm_chunk(const float* __restrict__ sA,
                                           const float* __restrict__ sW, int ldw,
                                           int tx, int rowbase, u64 acc[8][NQ])
{
    #pragma unroll 2
    for (int k0 = 0; k0 < KC; k0 += 4) {
        float4 av[8];
        #pragma unroll
        for (int r = 0; r < 8; r++)
            av[r] = *reinterpret_cast<const float4*>(sA + (rowbase + r) * LDAX + k0);
        #pragma unroll
        for (int kk = 0; kk < 4; kk++) {
            u64 b[NQ];
            #pragma unroll
            for (int q = 0; q < NQ; q += 2) {
                ulonglong2 bw = *reinterpret_cast<const ulonglong2*>(
                    sW + (k0 + kk) * ldw + tx * (NQ * 2) + q * 2);
                b[q] = bw.x; b[q + 1] = bw.y;
            }
            #pragma unroll
            for (int r = 0; r < 8; r++) {
                const float* ap = reinterpret_cast<const float*>(&av[r]);
                u64 a = dup2(ap[kk]);
                #pragma unroll
                for (int q = 0; q < NQ; q++)
                    acc[r][q] = ffma2(a, b[q], acc[r][q]);
            }
        }
    }
}

__device__ __forceinline__ void sts8(float* d, uint4 v) {
    *reinterpret_cast<float4*>(d)     = make_float4(blo(v.x), bhi(v.x), blo(v.y), bhi(v.y));
    *reinterpret_cast<float4*>(d + 4) = make_float4(blo(v.z), bhi(v.z), blo(v.w), bhi(v.w));
}

// ============ kernel 0: prep fused weights fw = l1w@W1, b1w = l1b@W1 ============
__global__ void k_prep(const float* __restrict__ l1w, const float* __restrict__ l1b,
                       const float* __restrict__ gw1)
{
    int b = blockIdx.x;
    if (b < 40) {
        int l = b >> 3, cpart = b & 7;
        for (int idx = threadIdx.x; idx < 1024; idx += 256) {
            int c = cpart * 8 + (idx >> 7), j = idx & 127;
            float s = 0.f;
            #pragma unroll 8
            for (int h = 0; h < 64; h++)
                s += l1w[l * 4096 + c * 64 + h] * gw1[h * 128 + j];
            fw_buf[l * 8192 + c * 128 + j] = s;
        }
    } else {
        if (threadIdx.x < 128) {
            float s = 0.f;
            #pragma unroll 8
            for (int h = 0; h < 64; h++)
                s += l1b[h] * gw1[h * 128 + threadIdx.x];
            b1w_buf[threadIdx.x] = s;
        }
    }
}

// ============ kernel 1 (FUSED): norm + gating + hw(smem) + g1 = silu(tg@hw) ============
// smem fl: SXN 3200 | STG 1600 | SHW 2x25x132=6600 | RED 64  = 11464 fl = 45856 B
#define SM_FR 11464
__global__ __launch_bounds__(256, 2)
void k_front(const float* __restrict__ x,
             const float* __restrict__ nl0w, const float* __restrict__ nl0b,
             const float* __restrict__ affw,
             const float* __restrict__ scw, const float* __restrict__ scb,
             const float* __restrict__ tg)
{
    extern __shared__ float smf[];
    float* SXN = smf;            // 3200
    float* STG = smf + 3200;     // 1600
    float* SHW = smf + 4800;     // 6600
    float* RED = smf + 11400;    // 64

    const int tid = threadIdx.x;
    const int half = tid >> 7, t = tid & 127;
    const long long n2 = blockIdx.x;

    const float4* xin = reinterpret_cast<const float4*>(x + n2 * 3200);
    for (int i = tid; i < 800; i += 256)
        reinterpret_cast<float4*>(SXN)[i] = xin[i];
    for (int i = tid; i < 1600; i += 256) STG[i] = tg[i];
    __syncthreads();

    float* sxn_h = SXN + half * 1600;

    // ---- stats ----
    {
        float s0 = 0.f, q0 = 0.f, fn = 0.f;
        for (int i = t; i < 1600; i += 128) {
            float v = sxn_h[i];
            int m = i >> 6;
            if (m == 0) { s0 += v; q0 += v * v; }
            else        { fn += c_bw[m] * v * v; }
        }
        #pragma unroll
        for (int off = 16; off > 0; off >>= 1) {
            s0 += __shfl_xor_sync(0xffffffffu, s0, off);
            q0 += __shfl_xor_sync(0xffffffffu, q0, off);
            fn += __shfl_xor_sync(0xffffffffu, fn, off);
        }
        int hw = (tid >> 5) & 3, lane = tid & 31;
        if (lane == 0) {
            RED[half * 32 + hw]      = s0;
            RED[half * 32 + 8 + hw]  = q0;
            RED[half * 32 + 16 + hw] = fn;
        }
        __syncthreads();
        if (t == 0) {
            float a = 0.f, b = 0.f, c = 0.f;
            #pragma unroll
            for (int w = 0; w < 4; w++) {
                a += RED[half * 32 + w];
                b += RED[half * 32 + 8 + w];
                c += RED[half * 32 + 16 + w];
            }
            float mu  = a * (1.f / 64.f);
            float var = b * (1.f / 64.f) - mu * mu;
            RED[half * 32 + 24] = mu;
            RED[half * 32 + 25] = rsqrtf(var + 1e-5f);
            RED[half * 32 + 26] = rsqrtf(c * (1.f / 64.f) + 1e-5f);
        }
        __syncthreads();
    }
    const float mu   = RED[half * 32 + 24];
    const float rstd = RED[half * 32 + 25];
    const float inv  = RED[half * 32 + 26];

    // ---- normalize ----
    for (int i = t; i < 1600; i += 128) {
        int m = i >> 6, cc = i & 63;
        float v = sxn_h[i];
        if (m == 0) v = (v - mu) * rstd * nl0w[cc] + nl0b[cc];
        else        v = v * inv * affw[(c_deg[m] - 1) * 64 + cc];
        sxn_h[i] = v;
    }
    __syncthreads();

    // ---- gating ----
    if (t < 64) {
        float acc = scb[t];
        #pragma unroll 8
        for (int i = 0; i < 64; i++) acc += sxn_h[i] * scw[i * 64 + t];
        gat_buf[(n2 * 2 + half) * 64 + t] = silu_f(acc);
    }

    // ---- hw = xn @ fw[deg] (+ b1w at row 0) -> SHW (stride 132) ----
    {
        const int j2 = t & 63, grp = t >> 6;   // 64 col-pairs, 2 row groups
        float* hout = SHW + half * 3300;
        for (int l = 0; l < 5; l++) {
            const int base = l * l, cnt = 2 * l + 1;
            int  rw[5];
            bool bv[5];
            #pragma unroll
            for (int s = 0; s < 5; s++) { rw[s] = base + grp + 2 * s; bv[s] = (grp + 2 * s) < cnt; }
            u64 a[5] = {};
            const float* w = fw_buf + l * 8192 + j2 * 2;
            for (int i0 = 0; i0 < 64; i0 += 4) {
                float4 va[5];
                #pragma unroll
                for (int s = 0; s < 5; s++)
                    if (bv[s]) va[s] = *reinterpret_cast<const float4*>(sxn_h + rw[s] * 64 + i0);
                #pragma unroll
                for (int kk = 0; kk < 4; kk++) {
                    u64 wv = *reinterpret_cast<const u64*>(w + (i0 + kk) * 128);
                    #pragma unroll
                    for (int s = 0; s < 5; s++)
                        if (bv[s]) a[s] = ffma2(dup2(reinterpret_cast<const float*>(&va[s])[kk]), wv, a[s]);
                }
            }
            #pragma unroll
            for (int s = 0; s < 5; s++) {
                if (bv[s]) {
                    float2 f = unpk(a[s]);
                    if (rw[s] == 0) { f.x += b1w_buf[j2 * 2]; f.y += b1w_buf[j2 * 2 + 1]; }
                    *reinterpret_cast<float2*>(hout + rw[s] * 132 + j2 * 2) = f;
                }
            }
        }
    }
    __syncthreads();

    // ---- g1 = silu(tg @ hw) -> g1_buf bf16 ----
    {
        const int smp = half;
        const int ty = t >> 4, tx = t & 15;
        const int sbase = ty * 8;
        const float* hwrow = SHW + smp * 3300 + tx * 8;

        u64 acc[8][4] = {};
        #pragma unroll 5
        for (int m = 0; m < 25; m++) {
            ulonglong2 b0 = *reinterpret_cast<const ulonglong2*>(hwrow + m * 132);
            ulonglong2 b1 = *reinterpret_cast<const ulonglong2*>(hwrow + m * 132 + 4);
            #pragma unroll
            for (int r = 0; r < 8; r++) {
                u64 a = dup2(STG[(sbase + r) * 25 + m]);
                acc[r][0] = ffma2(a, b0.x, acc[r][0]);
                acc[r][1] = ffma2(a, b0.y, acc[r][1]);
                acc[r][2] = ffma2(a, b1.x, acc[r][2]);
                acc[r][3] = ffma2(a, b1.y, acc[r][3]);
            }
        }

        u32* Ob = g1_buf + n2 * (128LL * 64);
        #pragma unroll
        for (int r = 0; r < 8; r++) {
            float2 f0 = unpk(acc[r][0]), f1 = unpk(acc[r][1]);
            float2 f2 = unpk(acc[r][2]), f3 = unpk(acc[r][3]);
            u32 p0 = bpack(silu_f(f0.x), silu_f(f0.y));
            u32 p1 = bpack(silu_f(f1.x), silu_f(f1.y));
            u32 p2 = bpack(silu_f(f2.x), silu_f(f2.y));
            u32 p3 = bpack(silu_f(f3.x), silu_f(f3.y));
            *reinterpret_cast<uint4*>(Ob + (smp * 64 + sbase + r) * 64 + tx * 4) =
                make_uint4(p0, p1, p2, p3);
        }
    }
}

// ============ kernel 2: g2 = silu(g1 @ W2), double-buffered A (R13 verbatim) ============
#define SM_G2 25600
__global__ __launch_bounds__(256, 2)
void k_g2(const float* __restrict__ W)
{
    extern __shared__ float smf[];
    float* sA0 = smf;
    float* sA1 = smf + 4608;
    float* sW  = smf + 9216;

    const int tid = threadIdx.x;
    const long long blk = blockIdx.x;
    const int ty = tid >> 4, tx = tid & 15;
    const int rowbase = ty * 8;
    const u32* Ab = g1_buf + blk * (128LL * 64);

    const int r0i = tid >> 2, c0i = tid & 3;
    const int r1i = (tid + 256) >> 2, c1i = (tid + 256) & 3;

    for (int i = tid; i < 4096; i += 256)
        reinterpret_cast<float4*>(sW)[i] = reinterpret_cast<const float4*>(W)[i];

    {
        uint4 va = *reinterpret_cast<const uint4*>(Ab + r0i * 64 + c0i * 4);
        uint4 vb = *reinterpret_cast<const uint4*>(Ab + r1i * 64 + c1i * 4);
        sts8(sA0 + r0i * LDA2 + c0i * 8, va);
        sts8(sA0 + r1i * LDA2 + c1i * 8, vb);
    }
    __syncthreads();

    float* bufs[2] = { sA0, sA1 };
    u64 acc[8][4] = {};
    #pragma unroll
    for (int kt = 0; kt < 4; kt++) {
        uint4 na, nb;
        if (kt < 3) {
            na = *reinterpret_cast<const uint4*>(Ab + r0i * 64 + (kt + 1) * 16 + c0i * 4);
            nb = *reinterpret_cast<const uint4*>(Ab + r1i * 64 + (kt + 1) * 16 + c1i * 4);
        }
        gemm_chunk<4, 32, LDA2>(bufs[kt & 1], sW + kt * 32 * 128, 128, tx, rowbase, acc);
        if (kt < 3) {
            float* nbuf = bufs[(kt + 1) & 1];
            sts8(nbuf + r0i * LDA2 + c0i * 8, na);
            sts8(nbuf + r1i * LDA2 + c1i * 8, nb);
        }
        __syncthreads();
    }

    u32* Ob = g2_buf + blk * (128LL * 64);
    #pragma unroll
    for (int r = 0; r < 8; r++) {
        float2 f0 = unpk(acc[r][0]), f1 = unpk(acc[r][1]);
        float2 f2 = unpk(acc[r][2]), f3 = unpk(acc[r][3]);
        u32 p0 = bpack(silu_f(f0.x), silu_f(f0.y));
        u32 p1 = bpack(silu_f(f1.x), silu_f(f1.y));
        u32 p2 = bpack(silu_f(f2.x), silu_f(f2.y));
        u32 p3 = bpack(silu_f(f3.x), silu_f(f3.y));
        *reinterpret_cast<uint4*>(Ob + (rowbase + r) * 64 + tx * 4) = make_uint4(p0, p1, p2, p3);
    }
}

// ============ kernel 3: factorized back (R13 verbatim) ============
#define SM_BK 24576
__global__ __launch_bounds__(256, 2)
void k_back(const float* __restrict__ W3,
            const float* __restrict__ l2w, const float* __restrict__ l2b,
            const float* __restrict__ tg, float* __restrict__ out)
{
    extern __shared__ float smf[];
    float* sG2  = smf;                       // [128][132]
    float* sW   = smf;                       // [0,8192) after g2 dead
    float* HBT  = smf + 8192;                // hb [2][25][64]
    u64*   sET  = (u64*)(smf + 16896);       // [2][12][128]
    float* STGS = smf + 23040;               // [64][24]

    const int tid = threadIdx.x;
    const long long n2 = blockIdx.x;
    const u32* Ab = g2_buf + n2 * (128LL * 64);

    for (int i = tid; i < 2048; i += 256) {
        int row = i >> 4, q = i & 15;
        uint4 v = *reinterpret_cast<const uint4*>(Ab + row * 64 + q * 4);
        sts8(sG2 + row * 132 + q * 8, v);
    }
    for (int i = tid; i < 1536; i += 256) {
        int s = i / 24, m1 = i - s * 24;
        STGS[i] = tg[s * 25 + 1 + m1];
    }
    __syncthreads();

    {
        const int smp = tid >> 7, t = tid & 127;
        const int cg = t & 31, mg = t >> 5;
        const float* g2s = sG2 + smp * 64 * 132 + cg * 4;
        u64 e[4][3] = {};
        for (int s = 0; s < 64; s++) {
            float4 a = *reinterpret_cast<const float4*>(g2s + s * 132);
            const float* tr = STGS + s * 24 + mg * 6;
            u64 b0 = *reinterpret_cast<const u64*>(tr);
            u64 b1 = *reinterpret_cast<const u64*>(tr + 2);
            u64 b2 = *reinterpret_cast<const u64*>(tr + 4);
            #pragma unroll
            for (int c = 0; c < 4; c++) {
                u64 av = dup2(reinterpret_cast<const float*>(&a)[c]);
                e[c][0] = ffma2(av, b0, e[c][0]);
                e[c][1] = ffma2(av, b1, e[c][1]);
                e[c][2] = ffma2(av, b2, e[c][2]);
            }
        }
        u64* et = sET + smp * 1536;
        #pragma unroll
        for (int j = 0; j < 3; j++)
            #pragma unroll
            for (int c = 0; c < 4; c++)
                et[(mg * 3 + j) * 128 + cg * 4 + c] = e[c][j];
    }
    __syncthreads();

    for (int i = tid; i < 2048; i += 256)
        reinterpret_cast<float4*>(sW)[i] = reinterpret_cast<const float4*>(W3)[i];
    if (tid < 128) HBT[(tid >> 6) * 1600 + (tid & 63)] = gat_buf[n2 * 128 + tid];
    __syncthreads();

    {
        const int smp = tid >> 7, t = tid & 127;
        const int cg = t & 31, mg = t >> 5;
        const u64* et = sET + smp * 1536;
        const u64* e0 = et + (mg * 3 + 0) * 128;
        const u64* e1 = et + (mg * 3 + 1) * 128;
        const u64* e2 = et + (mg * 3 + 2) * 128;
        const float* w = sW + cg * 2;
        u64 h00 = 0, h01 = 0, h02 = 0, h10 = 0, h11 = 0, h12 = 0;
        #pragma unroll 4
        for (int k = 0; k < 128; k++) {
            float2 wv = *reinterpret_cast<const float2*>(w + k * 64);
            u64 b0 = e0[k], b1 = e1[k], b2 = e2[k];
            u64 a0 = dup2(wv.x), a1 = dup2(wv.y);
            h00 = ffma2(a0, b0, h00); h01 = ffma2(a0, b1, h01); h02 = ffma2(a0, b2, h02);
            h10 = ffma2(a1, b0, h10); h11 = ffma2(a1, b1, h11); h12 = ffma2(a1, b2, h12);
        }
        float* hb = HBT + smp * 1600;
        const int c0 = cg * 2, m0 = 1 + mg * 6;
        float2 f;
        f = unpk(h00); hb[(m0 + 0) * 64 + c0] = f.x; hb[(m0 + 1) * 64 + c0] = f.y;
        f = unpk(h01); hb[(m0 + 2) * 64 + c0] = f.x; hb[(m0 + 3) * 64 + c0] = f.y;
        f = unpk(h02); hb[(m0 + 4) * 64 + c0] = f.x; hb[(m0 + 5) * 64 + c0] = f.y;
        f = unpk(h10); hb[(m0 + 0) * 64 + c0 + 1] = f.x; hb[(m0 + 1) * 64 + c0 + 1] = f.y;
        f = unpk(h11); hb[(m0 + 2) * 64 + c0 + 1] = f.x; hb[(m0 + 3) * 64 + c0 + 1] = f.y;
        f = unpk(h12); hb[(m0 + 4) * 64 + c0 + 1] = f.x; hb[(m0 + 5) * 64 + c0 + 1] = f.y;
    }
    __syncthreads();

    {
        const int smp = tid >> 7, t = tid & 127;
        const int j2 = t & 31, grp = t >> 5;
        const float* hb_h = HBT + smp * 1600;
        float* outn = out + (n2 * 2 + smp) * 1600;

        for (int i = tid; i < 2048; i += 256)
            reinterpret_cast<float4*>(sW)[i] = reinterpret_cast<const float4*>(l2w)[i];
        __syncthreads();

        #pragma unroll
        for (int piece = 0; piece < 3; piece++) {
            const int d0 = piece * 2;
            const int nl = (piece == 2) ? 1 : 2;
            if (piece > 0) {
                __syncthreads();
                for (int i = tid; i < nl * 1024; i += 256)
                    reinterpret_cast<float4*>(sW)[i] =
                        reinterpret_cast<const float4*>(l2w + d0 * 4096)[i];
                __syncthreads();
            }
            for (int li = 0; li < nl; li++) {
                const int l = d0 + li;
                const int base = l * l, cnt = 2 * l + 1;
                const int r0 = base + grp, r1 = r0 + 4, r2 = r1 + 4;
                const bool b0 = grp < cnt, b1 = grp + 4 < cnt, b2 = grp + 8 < cnt;
                u64 a0 = 0, a1 = 0, a2 = 0;
                const float* w = sW + li * 4096 + j2 * 2;
                #pragma unroll 4
                for (int i = 0; i < 64; i++) {
                    u64 wv = *reinterpret_cast<const u64*>(w + i * 64);
                    if (b0) a0 = ffma2(dup2(hb_h[r0 * 64 + i]), wv, a0);
                    if (b1) a1 = ffma2(dup2(hb_h[r1 * 64 + i]), wv, a1);
                    if (b2) a2 = ffma2(dup2(hb_h[r2 * 64 + i]), wv, a2);
                }
                if (b0) {
                    float2 f = unpk(a0);
                    if (r0 == 0) { f.x += l2b[j2 * 2]; f.y += l2b[j2 * 2 + 1]; }
                    *reinterpret_cast<float2*>(outn + r0 * 64 + j2 * 2) = f;
                }
                if (b1) *reinterpret_cast<float2*>(outn + r1 * 64 + j2 * 2) = unpk(a1);
                if (b2) *reinterpret_cast<float2*>(outn + r2 * 64 + j2 * 2) = unpk(a2);
            }
        }
    }
}

extern "C" void kernel_launch(void* const* d_in, const int* in_sizes, int n_in,
                              void* d_out, int out_size)
{
    const float* x    = (const float*)d_in[0];
    const float* nl0w = (const float*)d_in[1];
    const float* nl0b = (const float*)d_in[2];
    const float* affw = (const float*)d_in[3];
    const float* l1w  = (const float*)d_in[4];
    const float* l1b  = (const float*)d_in[5];
    const float* scw  = (const float*)d_in[6];
    const float* scb  = (const float*)d_in[7];
    const float* gw1  = (const float*)d_in[8];
    const float* gw2  = (const float*)d_in[9];
    const float* gw3  = (const float*)d_in[10];
    const float* l2w  = (const float*)d_in[11];
    const float* l2b  = (const float*)d_in[12];
    const float* tg   = (const float*)d_in[13];
    float* out = (float*)d_out;

    const int N = in_sizes[0] / 1600;
    const int NPAIR = N / 2;

    cudaFuncSetAttribute(k_front, cudaFuncAttributeMaxDynamicSharedMemorySize, SM_FR * 4);
    cudaFuncSetAttribute(k_g2,    cudaFuncAttributeMaxDynamicSharedMemorySize, SM_G2 * 4);
    cudaFuncSetAttribute(k_back,  cudaFuncAttributeMaxDynamicSharedMemorySize, SM_BK * 4);

    k_prep<<<41, 256>>>(l1w, l1b, gw1);
    k_front<<<NPAIR, 256, SM_FR * 4>>>(x, nl0w, nl0b, affw, scw, scb, tg);
    k_g2<<<NPAIR, 256, SM_G2 * 4>>>(gw2);
    k_back<<<NPAIR, 256, SM_BK * 4>>>(gw3, l2w, l2b, tg, out);
}

// round 16
// speedup vs baseline: 1.0503x; 1.0503x over previous
#include <cuda_runtime.h>
#include <math.h>

typedef unsigned long long u64;
typedef unsigned int u32;

// Scratch: N=20000
__device__ __align__(16) float h_buf[32000000];   // h (N,25,64) fp32
__device__ __align__(16) u32 g1_buf[81920000];    // g1 (N,64,128) bf16
__device__ __align__(16) u32 g2_buf[81920000];    // g2 (N,64,128) bf16
__device__ float gat_buf[1280000];                // gating (N,64)

__device__ __constant__ int c_deg[25] = {
    0, 1,1,1, 2,2,2,2,2, 3,3,3,3,3,3,3, 4,4,4,4,4,4,4,4,4
};
__device__ __constant__ float c_bw[25] = {
    0.f,
    1.f/12.f, 1.f/12.f, 1.f/12.f,
    1.f/20.f, 1.f/20.f, 1.f/20.f, 1.f/20.f, 1.f/20.f,
    1.f/28.f, 1.f/28.f, 1.f/28.f, 1.f/28.f, 1.f/28.f, 1.f/28.f, 1.f/28.f,
    1.f/36.f, 1.f/36.f, 1.f/36.f, 1.f/36.f, 1.f/36.f, 1.f/36.f, 1.f/36.f, 1.f/36.f, 1.f/36.f
};

__device__ __forceinline__ u64 ffma2(u64 a, u64 b, u64 c) {
    u64 d;
    asm("fma.rn.f32x2 %0, %1, %2, %3;" : "=l"(d) : "l"(a), "l"(b), "l"(c));
    return d;
}
__device__ __forceinline__ u64 dup2(float x) {
    u64 r; asm("mov.b64 %0, {%1, %1};" : "=l"(r) : "f"(x)); return r;
}
__device__ __forceinline__ float2 unpk(u64 v) {
    float2 f; asm("mov.b64 {%0, %1}, %2;" : "=f"(f.x), "=f"(f.y) : "l"(v)); return f;
}
__device__ __forceinline__ float silu_f(float v) {
    return v * (1.f / (1.f + __expf(-v)));
}
__device__ __forceinline__ u32 bpack(float lo, float hi) {
    u32 d; asm("cvt.rn.bf16x2.f32 %0, %1, %2;" : "=r"(d) : "f"(hi), "f"(lo)); return d;
}
__device__ __forceinline__ float blo(u32 p) { return __uint_as_float(p << 16); }
__device__ __forceinline__ float bhi(u32 p) { return __uint_as_float(p & 0xFFFF0000u); }

#define LDA  68
#define LDA2 36

template<int NQ, int KC, int LDAX>
__device__ __forceinline__ void gemm_chunk(const float* __restrict__ sA,
                                           const float* __restrict__ sW, int ldw,
                                           int tx, int rowbase, u64 acc[8][NQ])
{
    #pragma unroll 2
    for (int k0 = 0; k0 < KC; k0 += 4) {
        float4 av[8];
        #pragma unroll
        for (int r = 0; r < 8; r++)
            av[r] = *reinterpret_cast<const float4*>(sA + (rowbase + r) * LDAX + k0);
        #pragma unroll
        for (int kk = 0; kk < 4; kk++) {
            u64 b[NQ];
            #pragma unroll
            for (int q = 0; q < NQ; q += 2) {
                ulonglong2 bw = *reinterpret_cast<const ulonglong2*>(
                    sW + (k0 + kk) * ldw + tx * (NQ * 2) + q * 2);
                b[q] = bw.x; b[q + 1] = bw.y;
            }
            #pragma unroll
            for (int r = 0; r < 8; r++) {
                const float* ap = reinterpret_cast<const float*>(&av[r]);
                u64 a = dup2(ap[kk]);
                #pragma unroll
                for (int q = 0; q < NQ; q++)
                    acc[r][q] = ffma2(a, b[q], acc[r][q]);
            }
        }
    }
}

__device__ __forceinline__ void sts8(float* d, uint4 v) {
    *reinterpret_cast<float4*>(d)     = make_float4(blo(v.x), bhi(v.x), blo(v.y), bhi(v.y));
    *reinterpret_cast<float4*>(d + 4) = make_float4(blo(v.z), bhi(v.z), blo(v.w), bhi(v.w));
}

// ============ kernel 1: norm + gating + lin1 -> h_buf (R13 verbatim) ============
__global__ __launch_bounds__(256, 4)
void k_norm(const float* __restrict__ x,
            const float* __restrict__ nl0w, const float* __restrict__ nl0b,
            const float* __restrict__ affw,
            const float* __restrict__ l1w, const float* __restrict__ l1b,
            const float* __restrict__ scw, const float* __restrict__ scb)
{
    __shared__ float SXN[3200];
    __shared__ float RED[64];

    const int tid = threadIdx.x;
    const int half = tid >> 7, t = tid & 127;
    const long long n2 = blockIdx.x;

    const float4* xin = reinterpret_cast<const float4*>(x + n2 * 3200);
    for (int i = tid; i < 800; i += 256)
        reinterpret_cast<float4*>(SXN)[i] = xin[i];
    __syncthreads();

    float* sxn_h = SXN + half * 1600;

    {
        float s0 = 0.f, q0 = 0.f, fn = 0.f;
        for (int i = t; i < 1600; i += 128) {
            float v = sxn_h[i];
            int m = i >> 6;
            if (m == 0) { s0 += v; q0 += v * v; }
            else        { fn += c_bw[m] * v * v; }
        }
        #pragma unroll
        for (int off = 16; off > 0; off >>= 1) {
            s0 += __shfl_xor_sync(0xffffffffu, s0, off);
            q0 += __shfl_xor_sync(0xffffffffu, q0, off);
            fn += __shfl_xor_sync(0xffffffffu, fn, off);
        }
        int hw = (tid >> 5) & 3, lane = tid & 31;
        if (lane == 0) {
            RED[half * 32 + hw]      = s0;
            RED[half * 32 + 8 + hw]  = q0;
            RED[half * 32 + 16 + hw] = fn;
        }
        __syncthreads();
        if (t == 0) {
            float a = 0.f, b = 0.f, c = 0.f;
            #pragma unroll
            for (int w = 0; w < 4; w++) {
                a += RED[half * 32 + w];
                b += RED[half * 32 + 8 + w];
                c += RED[half * 32 + 16 + w];
            }
            float mu  = a * (1.f / 64.f);
            float var = b * (1.f / 64.f) - mu * mu;
            RED[half * 32 + 24] = mu;
            RED[half * 32 + 25] = rsqrtf(var + 1e-5f);
            RED[half * 32 + 26] = rsqrtf(c * (1.f / 64.f) + 1e-5f);
        }
        __syncthreads();
    }
    const float mu   = RED[half * 32 + 24];
    const float rstd = RED[half * 32 + 25];
    const float inv  = RED[half * 32 + 26];

    for (int i = t; i < 1600; i += 128) {
        int m = i >> 6, cc = i & 63;
        float v = sxn_h[i];
        if (m == 0) v = (v - mu) * rstd * nl0w[cc] + nl0b[cc];
        else        v = v * inv * affw[(c_deg[m] - 1) * 64 + cc];
        sxn_h[i] = v;
    }
    __syncthreads();

    if (t < 64) {
        float acc = scb[t];
        #pragma unroll 8
        for (int i = 0; i < 64; i++) acc += sxn_h[i] * scw[i * 64 + t];
        gat_buf[(n2 * 2 + half) * 64 + t] = silu_f(acc);
    }

    // lin1 -> h_buf (vectorized A reads)
    {
        const int j2 = t & 31, grp = t >> 5;
        float* hout = h_buf + (n2 * 2 + half) * 1600;
        for (int l = 0; l < 5; l++) {
            const int base = l * l, cnt = 2 * l + 1;
            const int r0 = base + grp, r1 = r0 + 4, r2 = r1 + 4;
            const bool b0 = grp < cnt, b1 = grp + 4 < cnt, b2 = grp + 8 < cnt;
            u64 a0 = 0, a1 = 0, a2 = 0;
            const float* w = l1w + l * 4096 + j2 * 2;
            for (int i0 = 0; i0 < 64; i0 += 4) {
                float4 va0, va1, va2;
                if (b0) va0 = *reinterpret_cast<const float4*>(sxn_h + r0 * 64 + i0);
                if (b1) va1 = *reinterpret_cast<const float4*>(sxn_h + r1 * 64 + i0);
                if (b2) va2 = *reinterpret_cast<const float4*>(sxn_h + r2 * 64 + i0);
                #pragma unroll
                for (int kk = 0; kk < 4; kk++) {
                    u64 wv = *reinterpret_cast<const u64*>(w + (i0 + kk) * 64);
                    if (b0) a0 = ffma2(dup2(reinterpret_cast<const float*>(&va0)[kk]), wv, a0);
                    if (b1) a1 = ffma2(dup2(reinterpret_cast<const float*>(&va1)[kk]), wv, a1);
                    if (b2) a2 = ffma2(dup2(reinterpret_cast<const float*>(&va2)[kk]), wv, a2);
                }
            }
            if (b0) {
                float2 f = unpk(a0);
                if (r0 == 0) { f.x += l1b[j2 * 2]; f.y += l1b[j2 * 2 + 1]; }
                *reinterpret_cast<float2*>(hout + r0 * 64 + j2 * 2) = f;
            }
            if (b1) *reinterpret_cast<float2*>(hout + r1 * 64 + j2 * 2) = unpk(a1);
            if (b2) *reinterpret_cast<float2*>(hout + r2 * 64 + j2 * 2) = unpk(a2);
        }
    }
}

// ============ kernel 2: to_grid + g1 GEMM (R13 verbatim) ============
#define SM_G1 21696
__global__ __launch_bounds__(256, 2)
void k_g1(const float* __restrict__ gw1, const float* __restrict__ tg)
{
    extern __shared__ float smf[];
    float* SH  = smf;            // 3200
    float* STG = smf + 3200;     // 1600
    float* SG  = smf + 4800;     // 8704
    float* SW  = smf + 13504;    // 8192

    const int tid = threadIdx.x;
    const long long n2 = blockIdx.x;
    const int ty = tid >> 4, tx = tid & 15;
    const int rowbase = ty * 8;

    const float4* hin = reinterpret_cast<const float4*>(h_buf + n2 * 3200);
    for (int i = tid; i < 800; i += 256)
        reinterpret_cast<float4*>(SH)[i] = hin[i];
    for (int i = tid; i < 1600; i += 256) STG[i] = tg[i];
    for (int i = tid; i < 2048; i += 256)
        reinterpret_cast<float4*>(SW)[i] = reinterpret_cast<const float4*>(gw1)[i];
    __syncthreads();

    {
        const float* shh = SH + (ty >= 8 ? 1600 : 0);
        const int sbase = (ty & 7) * 8;
        u64 acc[8][2] = {};
        for (int m = 0; m < 25; m++) {
            u64 bv0 = *reinterpret_cast<const u64*>(shh + m * 64 + tx * 4);
            u64 bv1 = *reinterpret_cast<const u64*>(shh + m * 64 + tx * 4 + 2);
            #pragma unroll
            for (int r = 0; r < 8; r++) {
                u64 a = dup2(STG[(sbase + r) * 25 + m]);
                acc[r][0] = ffma2(a, bv0, acc[r][0]);
                acc[r][1] = ffma2(a, bv1, acc[r][1]);
            }
        }
        #pragma unroll
        for (int r = 0; r < 8; r++) {
            float2 f0 = unpk(acc[r][0]), f1 = unpk(acc[r][1]);
            *reinterpret_cast<float4*>(SG + (rowbase + r) * LDA + tx * 4) =
                make_float4(f0.x, f0.y, f1.x, f1.y);
        }
    }
    __syncthreads();

    {
        u64 acc[8][4] = {};
        gemm_chunk<4, 64, LDA>(SG, SW, 128, tx, rowbase, acc);
        u32* Ob = g1_buf + n2 * (128LL * 64);
        #pragma unroll
        for (int r = 0; r < 8; r++) {
            float2 f0 = unpk(acc[r][0]), f1 = unpk(acc[r][1]);
            float2 f2 = unpk(acc[r][2]), f3 = unpk(acc[r][3]);
            u32 p0 = bpack(silu_f(f0.x), silu_f(f0.y));
            u32 p1 = bpack(silu_f(f1.x), silu_f(f1.y));
            u32 p2 = bpack(silu_f(f2.x), silu_f(f2.y));
            u32 p3 = bpack(silu_f(f3.x), silu_f(f3.y));
            *reinterpret_cast<uint4*>(Ob + (rowbase + r) * 64 + tx * 4) = make_uint4(p0, p1, p2, p3);
        }
    }
}

// ============ kernel 3: g2 = silu(g1 @ W2), double-buffered A (R13 verbatim) ============
#define SM_G2 25600
__global__ __launch_bounds__(256, 2)
void k_g2(const float* __restrict__ W)
{
    extern __shared__ float smf[];
    float* sA0 = smf;
    float* sA1 = smf + 4608;
    float* sW  = smf + 9216;

    const int tid = threadIdx.x;
    const long long blk = blockIdx.x;
    const int ty = tid >> 4, tx = tid & 15;
    const int rowbase = ty * 8;
    const u32* Ab = g1_buf + blk * (128LL * 64);

    const int r0i = tid >> 2, c0i = tid & 3;
    const int r1i = (tid + 256) >> 2, c1i = (tid + 256) & 3;

    for (int i = tid; i < 4096; i += 256)
        reinterpret_cast<float4*>(sW)[i] = reinterpret_cast<const float4*>(W)[i];

    {
        uint4 va = *reinterpret_cast<const uint4*>(Ab + r0i * 64 + c0i * 4);
        uint4 vb = *reinterpret_cast<const uint4*>(Ab + r1i * 64 + c1i * 4);
        sts8(sA0 + r0i * LDA2 + c0i * 8, va);
        sts8(sA0 + r1i * LDA2 + c1i * 8, vb);
    }
    __syncthreads();

    float* bufs[2] = { sA0, sA1 };
    u64 acc[8][4] = {};
    #pragma unroll
    for (int kt = 0; kt < 4; kt++) {
        uint4 na, nb;
        if (kt < 3) {
            na = *reinterpret_cast<const uint4*>(Ab + r0i * 64 + (kt + 1) * 16 + c0i * 4);
            nb = *reinterpret_cast<const uint4*>(Ab + r1i * 64 + (kt + 1) * 16 + c1i * 4);
        }
        gemm_chunk<4, 32, LDA2>(bufs[kt & 1], sW + kt * 32 * 128, 128, tx, rowbase, acc);
        if (kt < 3) {
            float* nbuf = bufs[(kt + 1) & 1];
            sts8(nbuf + r0i * LDA2 + c0i * 8, na);
            sts8(nbuf + r1i * LDA2 + c1i * 8, nb);
        }
        __syncthreads();
    }

    u32* Ob = g2_buf + blk * (128LL * 64);
    #pragma unroll
    for (int r = 0; r < 8; r++) {
        float2 f0 = unpk(acc[r][0]), f1 = unpk(acc[r][1]);
        float2 f2 = unpk(acc[r][2]), f3 = unpk(acc[r][3]);
        u32 p0 = bpack(silu_f(f0.x), silu_f(f0.y));
        u32 p1 = bpack(silu_f(f1.x), silu_f(f1.y));
        u32 p2 = bpack(silu_f(f2.x), silu_f(f2.y));
        u32 p3 = bpack(silu_f(f3.x), silu_f(f3.y));
        *reinterpret_cast<uint4*>(Ob + (rowbase + r) * 64 + tx * 4) = make_uint4(p0, p1, p2, p3);
    }
}

// ============ kernel 4: factorized back (R13 + vectorized lin2/phase4) ============
#define SM_BK 24576
__global__ __launch_bounds__(256, 2)
void k_back(const float* __restrict__ W3,
            const float* __restrict__ l2w, const float* __restrict__ l2b,
            const float* __restrict__ tg, float* __restrict__ out)
{
    extern __shared__ float smf[];
    float* sG2  = smf;                       // [128][132]
    float* sW   = smf;                       // [0,8192) after g2 dead
    float* HBT  = smf + 8192;                // hb [2][25][64]
    u64*   sET  = (u64*)(smf + 16896);       // [2][12][128]
    float* STGS = smf + 23040;               // [64][24]

    const int tid = threadIdx.x;
    const long long n2 = blockIdx.x;
    const u32* Ab = g2_buf + n2 * (128LL * 64);

    for (int i = tid; i < 2048; i += 256) {
        int row = i >> 4, q = i & 15;
        uint4 v = *reinterpret_cast<const uint4*>(Ab + row * 64 + q * 4);
        sts8(sG2 + row * 132 + q * 8, v);
    }
    for (int i = tid; i < 1536; i += 256) {
        int s = i / 24, m1 = i - s * 24;
        STGS[i] = tg[s * 25 + 1 + m1];
    }
    __syncthreads();

    // phase 2: E^T = tg^T-products (R13 verbatim)
    {
        const int smp = tid >> 7, t = tid & 127;
        const int cg = t & 31, mg = t >> 5;
        const float* g2s = sG2 + smp * 64 * 132 + cg * 4;
        u64 e[4][3] = {};
        for (int s = 0; s < 64; s++) {
            float4 a = *reinterpret_cast<const float4*>(g2s + s * 132);
            const float* tr = STGS + s * 24 + mg * 6;
            u64 b0 = *reinterpret_cast<const u64*>(tr);
            u64 b1 = *reinterpret_cast<const u64*>(tr + 2);
            u64 b2 = *reinterpret_cast<const u64*>(tr + 4);
            #pragma unroll
            for (int c = 0; c < 4; c++) {
                u64 av = dup2(reinterpret_cast<const float*>(&a)[c]);
                e[c][0] = ffma2(av, b0, e[c][0]);
                e[c][1] = ffma2(av, b1, e[c][1]);
                e[c][2] = ffma2(av, b2, e[c][2]);
            }
        }
        u64* et = sET + smp * 1536;
        #pragma unroll
        for (int j = 0; j < 3; j++)
            #pragma unroll
            for (int c = 0; c < 4; c++)
                et[(mg * 3 + j) * 128 + cg * 4 + c] = e[c][j];
    }
    __syncthreads();

    for (int i = tid; i < 2048; i += 256)
        reinterpret_cast<float4*>(sW)[i] = reinterpret_cast<const float4*>(W3)[i];
    if (tid < 128) HBT[(tid >> 6) * 1600 + (tid & 63)] = gat_buf[n2 * 128 + tid];
    __syncthreads();

    // phase 4: hb = E@W3 with k-pair-vectorized E loads
    {
        const int smp = tid >> 7, t = tid & 127;
        const int cg = t & 31, mg = t >> 5;
        const u64* et = sET + smp * 1536;
        const u64* e0 = et + (mg * 3 + 0) * 128;
        const u64* e1 = et + (mg * 3 + 1) * 128;
        const u64* e2 = et + (mg * 3 + 2) * 128;
        const float* w = sW + cg * 2;
        u64 h00 = 0, h01 = 0, h02 = 0, h10 = 0, h11 = 0, h12 = 0;
        #pragma unroll 2
        for (int k = 0; k < 128; k += 2) {
            float2 wv0 = *reinterpret_cast<const float2*>(w + k * 64);
            float2 wv1 = *reinterpret_cast<const float2*>(w + (k + 1) * 64);
            ulonglong2 p0 = *reinterpret_cast<const ulonglong2*>(e0 + k);
            ulonglong2 p1 = *reinterpret_cast<const ulonglong2*>(e1 + k);
            ulonglong2 p2 = *reinterpret_cast<const ulonglong2*>(e2 + k);
            u64 a0 = dup2(wv0.x), a1 = dup2(wv0.y);
            h00 = ffma2(a0, p0.x, h00); h01 = ffma2(a0, p1.x, h01); h02 = ffma2(a0, p2.x, h02);
            h10 = ffma2(a1, p0.x, h10); h11 = ffma2(a1, p1.x, h11); h12 = ffma2(a1, p2.x, h12);
            u64 a2 = dup2(wv1.x), a3 = dup2(wv1.y);
            h00 = ffma2(a2, p0.y, h00); h01 = ffma2(a2, p1.y, h01); h02 = ffma2(a2, p2.y, h02);
            h10 = ffma2(a3, p0.y, h10); h11 = ffma2(a3, p1.y, h11); h12 = ffma2(a3, p2.y, h12);
        }
        float* hb = HBT + smp * 1600;
        const int c0 = cg * 2, m0 = 1 + mg * 6;
        float2 f;
        f = unpk(h00); hb[(m0 + 0) * 64 + c0] = f.x; hb[(m0 + 1) * 64 + c0] = f.y;
        f = unpk(h01); hb[(m0 + 2) * 64 + c0] = f.x; hb[(m0 + 3) * 64 + c0] = f.y;
        f = unpk(h02); hb[(m0 + 4) * 64 + c0] = f.x; hb[(m0 + 5) * 64 + c0] = f.y;
        f = unpk(h10); hb[(m0 + 0) * 64 + c0 + 1] = f.x; hb[(m0 + 1) * 64 + c0 + 1] = f.y;
        f = unpk(h11); hb[(m0 + 2) * 64 + c0 + 1] = f.x; hb[(m0 + 3) * 64 + c0 + 1] = f.y;
        f = unpk(h12); hb[(m0 + 4) * 64 + c0 + 1] = f.x; hb[(m0 + 5) * 64 + c0 + 1] = f.y;
    }
    __syncthreads();

    // phase 5: lin2 with float4-over-i vectorized hb loads
    {
        const int smp = tid >> 7, t = tid & 127;
        const int j2 = t & 31, grp = t >> 5;
        const float* hb_h = HBT + smp * 1600;
        float* outn = out + (n2 * 2 + smp) * 1600;

        for (int i = tid; i < 2048; i += 256)
            reinterpret_cast<float4*>(sW)[i] = reinterpret_cast<const float4*>(l2w)[i];
        __syncthreads();

        #pragma unroll
        for (int piece = 0; piece < 3; piece++) {
            const int d0 = piece * 2;
            const int nl = (piece == 2) ? 1 : 2;
            if (piece > 0) {
                __syncthreads();
                for (int i = tid; i < nl * 1024; i += 256)
                    reinterpret_cast<float4*>(sW)[i] =
                        reinterpret_cast<const float4*>(l2w + d0 * 4096)[i];
                __syncthreads();
            }
            for (int li = 0; li < nl; li++) {
                const int l = d0 + li;
                const int base = l * l, cnt = 2 * l + 1;
                const int r0 = base + grp, r1 = r0 + 4, r2 = r1 + 4;
                const bool b0 = grp < cnt, b1 = grp + 4 < cnt, b2 = grp + 8 < cnt;
                u64 a0 = 0, a1 = 0, a2 = 0;
                const float* w = sW + li * 4096 + j2 * 2;
                for (int i0 = 0; i0 < 64; i0 += 4) {
                    float4 va0, va1, va2;
                    if (b0) va0 = *reinterpret_cast<const float4*>(hb_h + r0 * 64 + i0);
                    if (b1) va1 = *reinterpret_cast<const float4*>(hb_h + r1 * 64 + i0);
                    if (b2) va2 = *reinterpret_cast<const float4*>(hb_h + r2 * 64 + i0);
                    #pragma unroll
                    for (int kk = 0; kk < 4; kk++) {
                        u64 wv = *reinterpret_cast<const u64*>(w + (i0 + kk) * 64);
                        if (b0) a0 = ffma2(dup2(reinterpret_cast<const float*>(&va0)[kk]), wv, a0);
                        if (b1) a1 = ffma2(dup2(reinterpret_cast<const float*>(&va1)[kk]), wv, a1);
                        if (b2) a2 = ffma2(dup2(reinterpret_cast<const float*>(&va2)[kk]), wv, a2);
                    }
                }
                if (b0) {
                    float2 f = unpk(a0);
                    if (r0 == 0) { f.x += l2b[j2 * 2]; f.y += l2b[j2 * 2 + 1]; }
                    *reinterpret_cast<float2*>(outn + r0 * 64 + j2 * 2) = f;
                }
                if (b1) *reinterpret_cast<float2*>(outn + r1 * 64 + j2 * 2) = unpk(a1);
                if (b2) *reinterpret_cast<float2*>(outn + r2 * 64 + j2 * 2) = unpk(a2);
            }
        }
    }
}

extern "C" void kernel_launch(void* const* d_in, const int* in_sizes, int n_in,
                              void* d_out, int out_size)
{
    const float* x    = (const float*)d_in[0];
    const float* nl0w = (const float*)d_in[1];
    const float* nl0b = (const float*)d_in[2];
    const float* affw = (const float*)d_in[3];
    const float* l1w  = (const float*)d_in[4];
    const float* l1b  = (const float*)d_in[5];
    const float* scw  = (const float*)d_in[6];
    const float* scb  = (const float*)d_in[7];
    const float* gw1  = (const float*)d_in[8];
    const float* gw2  = (const float*)d_in[9];
    const float* gw3  = (const float*)d_in[10];
    const float* l2w  = (const float*)d_in[11];
    const float* l2b  = (const float*)d_in[12];
    const float* tg   = (const float*)d_in[13];
    float* out = (float*)d_out;

    const int N = in_sizes[0] / 1600;
    const int NPAIR = N / 2;

    cudaFuncSetAttribute(k_g1,   cudaFuncAttributeMaxDynamicSharedMemorySize, SM_G1 * 4);
    cudaFuncSetAttribute(k_g2,   cudaFuncAttributeMaxDynamicSharedMemorySize, SM_G2 * 4);
    cudaFuncSetAttribute(k_back, cudaFuncAttributeMaxDynamicSharedMemorySize, SM_BK * 4);

    k_norm<<<NPAIR, 256>>>(x, nl0w, nl0b, affw, l1w, l1b, scw, scb);
    k_g1<<<NPAIR, 256, SM_G1 * 4>>>(gw1, tg);
    k_g2<<<NPAIR, 256, SM_G2 * 4>>>(gw2);
    k_back<<<NPAIR, 256, SM_BK * 4>>>(gw3, l2w, l2b, tg, out);
}